// round 11
// baseline (speedup 1.0000x reference)
#include <cuda_runtime.h>
#include <math.h>
#include <stdint.h>
#include <mma.h>

using namespace nvcuda;

// ---------------------------------------------------------------------------
// HashMoELayer: shared SwiGLU expert + 2x hash-routed GELU experts (E=8).
// Routing hash (tok*11 + k*7919) % 8 depends only on tok mod 8:
//   k=0: e = (3*r) % 8,  k=1: e = (3*r + 7) % 8  => stride-8 token groups.
// tf32 wmma tensor-core GEMMs, fp32 accumulate.
// R11: cp.async double-buffered mainloop (overlap gmem with MMA),
//      fragment-side tf32 rounding, epilogue staging aliases As.
// ---------------------------------------------------------------------------

#define BM 128
#define BN 128
#define BK 32
// 8 warps: 4 (m) x 2 (n); warp tile 32x64 = 2x4 fragments of 16x16

#define NTOK  32768
#define CDIM  1024
#define HS    2048
#define HR    1024
#define MPG   4096

#define STLD  20                 // staging ldm, multiple of 4 (wmma requirement)
#define ALD   (BK + 4)           // 36
#define BLD   (BN + 4)           // 132
#define SMEM_FLOATS (2*BM*ALD + 2*BK*BLD)   // 9216 + 8448 = 17664
#define SMEM_BYTES  (SMEM_FLOATS * 4)       // 70656

// Scratch (device globals; no allocation allowed)
__device__ float g_g1[(size_t)NTOK * HS];
__device__ float g_g3[(size_t)NTOK * HS];
__device__ float g_h [(size_t)NTOK * HR];

__device__ __forceinline__ void cp_async16(uint32_t dst, const float* src) {
    asm volatile("cp.async.cg.shared.global [%0], [%1], 16;\n" :: "r"(dst), "l"(src));
}
__device__ __forceinline__ void cp_commit() {
    asm volatile("cp.async.commit_group;\n");
}
template<int N> __device__ __forceinline__ void cp_wait() {
    asm volatile("cp.async.wait_group %0;\n" :: "n"(N));
}

// MODE:
//  0 : C[row]        = acc + bias
//  2 : C[row]        = 0.5f*(acc + bias)
//  3 : C[g*M + row]  = gelu(acc + bias), A gathered: token = g + 8*(m0+row)
//  4 : C[g + 8*row] += 0.25f*(acc + bias), A contiguous grouped rows
template<int MODE>
__global__ void __launch_bounds__(256, 2)
gemm_tc(int M, int N, int K,
        const float* __restrict__ A,
        const float* __restrict__ B,
        const float* __restrict__ bias,
        float* __restrict__ C,
        int phase7)
{
    extern __shared__ float sm[];
    float (*As)[BM][ALD]  = (float(*)[BM][ALD])sm;                    // [2][128][36]
    float (*Bs)[BK][BLD]  = (float(*)[BK][BLD])(sm + 2 * BM * ALD);   // [2][32][132]
    float (*St)[16][STLD] = (float(*)[16][STLD])sm;                   // aliases As (epilogue only)

    const int tid  = threadIdx.x;
    const int wid  = tid >> 5;
    const int lane = tid & 31;
    const int wm   = wid >> 1;           // 0..3
    const int wn   = wid & 1;            // 0..1

    const int grp = blockIdx.z;
    const int m0  = blockIdx.y * BM;
    const int n0  = blockIdx.x * BN;

    const float* Bp    = B;
    const float* biasp = bias;
    if (MODE == 3 || MODE == 4) {
        int e = (3 * grp + phase7) & 7;
        Bp    = B    + (size_t)e * K * N;
        biasp = bias + (size_t)e * N;
    }

    // ---- loader mapping ----
    // A: 128x32 tile, 2 threads/row, 16 floats (4x cp.async) each
    const int ar = tid >> 1;
    const int ac = (tid & 1) * 16;
    size_t a_row_g;
    if      (MODE == 3) a_row_g = (size_t)grp + 8u * (size_t)(m0 + ar);
    else if (MODE == 4) a_row_g = (size_t)grp * M + (size_t)(m0 + ar);
    else                a_row_g = (size_t)(m0 + ar);
    const float* Arow = A + a_row_g * (size_t)K + ac;

    // B: 32x128 tile, 8 threads/row, 16 floats (4x cp.async) each
    const int br = tid >> 3;
    const int bc = (tid & 7) * 16;
    const float* Bpos = Bp + (size_t)br * N + n0 + bc;

    uint32_t a_dst[2], b_dst[2];
    #pragma unroll
    for (int s = 0; s < 2; s++) {
        a_dst[s] = (uint32_t)__cvta_generic_to_shared(&As[s][ar][ac]);
        b_dst[s] = (uint32_t)__cvta_generic_to_shared(&Bs[s][br][bc]);
    }

    wmma::fragment<wmma::accumulator, 16, 16, 8, float> acc[2][4];
    #pragma unroll
    for (int i = 0; i < 2; i++)
        #pragma unroll
        for (int j = 0; j < 4; j++) wmma::fill_fragment(acc[i][j], 0.0f);

    const int ktiles = K / BK;

    // prologue: stage tile 0 into buffer 0
    #pragma unroll
    for (int q = 0; q < 4; q++) cp_async16(a_dst[0] + q * 16, Arow + q * 4);
    #pragma unroll
    for (int q = 0; q < 4; q++) cp_async16(b_dst[0] + q * 16, Bpos + q * 4);
    cp_commit();

    for (int t = 0; t < ktiles; t++) {
        const int buf = t & 1;
        if (t + 1 < ktiles) {
            const int nb = buf ^ 1;
            const int k1 = (t + 1) * BK;
            #pragma unroll
            for (int q = 0; q < 4; q++) cp_async16(a_dst[nb] + q * 16, Arow + k1 + q * 4);
            #pragma unroll
            for (int q = 0; q < 4; q++) cp_async16(b_dst[nb] + q * 16, Bpos + (size_t)k1 * N + q * 4);
            cp_commit();
            cp_wait<1>();
        } else {
            cp_wait<0>();
        }
        __syncthreads();

        #pragma unroll
        for (int kk = 0; kk < BK / 8; kk++) {
            wmma::fragment<wmma::matrix_a, 16, 16, 8, wmma::precision::tf32, wmma::row_major> af[2];
            wmma::fragment<wmma::matrix_b, 16, 16, 8, wmma::precision::tf32, wmma::row_major> bf[4];
            #pragma unroll
            for (int i = 0; i < 2; i++) {
                wmma::load_matrix_sync(af[i], &As[buf][wm * 32 + i * 16][kk * 8], ALD);
                #pragma unroll
                for (int e = 0; e < af[i].num_elements; e++)
                    af[i].x[e] = wmma::__float_to_tf32(af[i].x[e]);
            }
            #pragma unroll
            for (int j = 0; j < 4; j++) {
                wmma::load_matrix_sync(bf[j], &Bs[buf][kk * 8][wn * 64 + j * 16], BLD);
                #pragma unroll
                for (int e = 0; e < bf[j].num_elements; e++)
                    bf[j].x[e] = wmma::__float_to_tf32(bf[j].x[e]);
            }
            #pragma unroll
            for (int i = 0; i < 2; i++)
                #pragma unroll
                for (int j = 0; j < 4; j++)
                    wmma::mma_sync(acc[i][j], af[i], bf[j], acc[i][j]);
        }
        __syncthreads();
    }

    // ---- epilogue: per-fragment staging (St aliases As; mainloop fully synced) ----
    const int sr = lane >> 1;
    const int sc = (lane & 1) * 8;

    #pragma unroll
    for (int i = 0; i < 2; i++) {
        #pragma unroll
        for (int j = 0; j < 4; j++) {
            wmma::store_matrix_sync(&St[wid][0][0], acc[i][j], STLD, wmma::mem_row_major);
            __syncwarp();

            const int rl   = wm * 32 + i * 16 + sr;
            const int ncol = n0 + wn * 64 + j * 16 + sc;

            size_t crow;
            if      (MODE == 3) crow = (size_t)grp * M + (size_t)(m0 + rl);
            else if (MODE == 4) crow = (size_t)grp + 8u * (size_t)(m0 + rl);
            else                crow = (size_t)(m0 + rl);
            float* Cp = C + crow * (size_t)N + ncol;

            float v[8];
            #pragma unroll
            for (int q = 0; q < 8; q++)
                v[q] = St[wid][sr][sc + q] + biasp[ncol + q];

            if (MODE == 4) {
                float4 c0 = *(float4*)Cp;
                float4 c1 = *(float4*)(Cp + 4);
                c0.x += 0.25f * v[0]; c0.y += 0.25f * v[1];
                c0.z += 0.25f * v[2]; c0.w += 0.25f * v[3];
                c1.x += 0.25f * v[4]; c1.y += 0.25f * v[5];
                c1.z += 0.25f * v[6]; c1.w += 0.25f * v[7];
                *(float4*)Cp       = c0;
                *(float4*)(Cp + 4) = c1;
            } else {
                #pragma unroll
                for (int q = 0; q < 8; q++) {
                    if (MODE == 2) v[q] = 0.5f * v[q];
                    if (MODE == 3) v[q] = 0.5f * v[q] * (1.0f + erff(v[q] * 0.70710678118654752f));
                }
                *(float4*)Cp       = make_float4(v[0], v[1], v[2], v[3]);
                *(float4*)(Cp + 4) = make_float4(v[4], v[5], v[6], v[7]);
            }
            __syncwarp();
        }
    }
}

// g1 = silu(g1) * g3, elementwise (float4)
__global__ void __launch_bounds__(256)
silu_mul_k(float* __restrict__ g1, const float* __restrict__ g3, size_t n4)
{
    size_t i = (size_t)blockIdx.x * blockDim.x + threadIdx.x;
    if (i < n4) {
        float4 a = ((float4*)g1)[i];
        float4 b = ((const float4*)g3)[i];
        a.x = (a.x / (1.f + expf(-a.x))) * b.x;
        a.y = (a.y / (1.f + expf(-a.y))) * b.y;
        a.z = (a.z / (1.f + expf(-a.z))) * b.z;
        a.w = (a.w / (1.f + expf(-a.w))) * b.w;
        ((float4*)g1)[i] = a;
    }
}

extern "C" void kernel_launch(void* const* d_in, const int* in_sizes, int n_in,
                              void* d_out, int out_size)
{
    const float* x   = (const float*)d_in[0];
    // d_in[1] = t_emb (unused by the reference)
    const float* sw1 = (const float*)d_in[2];
    const float* sb1 = (const float*)d_in[3];
    const float* sw3 = (const float*)d_in[4];
    const float* sb3 = (const float*)d_in[5];
    const float* sw2 = (const float*)d_in[6];
    const float* sb2 = (const float*)d_in[7];
    const float* w1  = (const float*)d_in[8];
    const float* b1  = (const float*)d_in[9];
    const float* w2  = (const float*)d_in[10];
    const float* b2  = (const float*)d_in[11];
    float* out = (float*)d_out;

    float *g1p, *g3p, *hp;
    cudaGetSymbolAddress((void**)&g1p, g_g1);
    cudaGetSymbolAddress((void**)&g3p, g_g3);
    cudaGetSymbolAddress((void**)&hp,  g_h);

    // allow >48KB dynamic smem (host attribute, idempotent, not an allocation)
    cudaFuncSetAttribute(gemm_tc<0>, cudaFuncAttributeMaxDynamicSharedMemorySize, SMEM_BYTES);
    cudaFuncSetAttribute(gemm_tc<2>, cudaFuncAttributeMaxDynamicSharedMemorySize, SMEM_BYTES);
    cudaFuncSetAttribute(gemm_tc<3>, cudaFuncAttributeMaxDynamicSharedMemorySize, SMEM_BYTES);
    cudaFuncSetAttribute(gemm_tc<4>, cudaFuncAttributeMaxDynamicSharedMemorySize, SMEM_BYTES);

    const dim3 blk(256);

    // Shared SwiGLU: g1 = x@sw1+sb1 ; g3 = x@sw3+sb3
    gemm_tc<0><<<dim3(HS / BN, NTOK / BM, 1), blk, SMEM_BYTES>>>(NTOK, HS, CDIM, x, sw1, sb1, g1p, 0);
    gemm_tc<0><<<dim3(HS / BN, NTOK / BM, 1), blk, SMEM_BYTES>>>(NTOK, HS, CDIM, x, sw3, sb3, g3p, 0);

    // g1 = silu(g1)*g3
    const size_t n4 = (size_t)NTOK * HS / 4;
    silu_mul_k<<<(unsigned)((n4 + 255) / 256), blk>>>(g1p, g3p, n4);

    // out = 0.5*(g1@sw2 + sb2)
    gemm_tc<2><<<dim3(CDIM / BN, NTOK / BM, 1), blk, SMEM_BYTES>>>(NTOK, CDIM, HS, g1p, sw2, sb2, out, 0);

    // Routed experts, k = 0 (phase 0) and k = 1 (phase 7)
    for (int phase = 0; phase <= 7; phase += 7) {
        gemm_tc<3><<<dim3(HR / BN, MPG / BM, 8), blk, SMEM_BYTES>>>(MPG, HR, CDIM, x, w1, b1, hp, phase);
        gemm_tc<4><<<dim3(CDIM / BN, MPG / BM, 8), blk, SMEM_BYTES>>>(MPG, CDIM, HR, hp, w2, b2, out, phase);
    }
}

// round 16
// speedup vs baseline: 1.5685x; 1.5685x over previous
#include <cuda_runtime.h>
#include <math.h>
#include <stdint.h>
#include <mma.h>

using namespace nvcuda;

// ---------------------------------------------------------------------------
// HashMoELayer: shared SwiGLU expert + 2x hash-routed GELU experts (E=8).
// Routing hash (tok*11 + k*7919) % 8 depends only on tok mod 8:
//   k=0: e = (3*r) % 8,  k=1: e = (3*r + 7) % 8  => stride-8 token groups.
// tf32 wmma tensor-core GEMMs, fp32 accumulate.
// R15 (= R14 resubmit after infra failure): all GEMM operands pre-rounded to
// tf32 (rna) by producers, so the cp.async double-buffered mainloop has ZERO
// conversions on the LDS->HMMA critical path. Numerics identical to R10.
// ---------------------------------------------------------------------------

#define BM 128
#define BN 128
#define BK 32
// 8 warps: 4 (m) x 2 (n); warp tile 32x64 = 2x4 fragments of 16x16

#define NTOK  32768
#define CDIM  1024
#define HS    2048
#define HR    1024
#define MPG   4096

#define STLD  20                 // staging ldm, multiple of 4 (wmma requirement)
#define ALD   (BK + 4)           // 36
#define BLD   (BN + 4)           // 132
#define SMEM_FLOATS (2*BM*ALD + 2*BK*BLD)   // 17664
#define SMEM_BYTES  (SMEM_FLOATS * 4)       // 70656

// rounded-weight scratch offsets (floats), layouts unchanged ([K,N] / [E,K,N])
#define OFF_SW1  0
#define OFF_SW3  (CDIM*HS)
#define OFF_SW2  (2*CDIM*HS)
#define OFF_W1   (3*CDIM*HS)
#define OFF_W2   (3*CDIM*HS + 8*CDIM*HR)
#define WT_TOTAL (3*CDIM*HS + 16*CDIM*HR)

// Scratch (device globals; no allocation allowed)
__device__ float g_g1[(size_t)NTOK * HS];
__device__ float g_g3[(size_t)NTOK * HS];
__device__ float g_h [(size_t)NTOK * HR];
__device__ float g_wT[(size_t)WT_TOTAL];
__device__ float g_xr[(size_t)NTOK * CDIM];

__device__ __forceinline__ void cp_async16(uint32_t dst, const float* src) {
    asm volatile("cp.async.cg.shared.global [%0], [%1], 16;\n" :: "r"(dst), "l"(src));
}
__device__ __forceinline__ void cp_commit() {
    asm volatile("cp.async.commit_group;\n");
}
template<int N> __device__ __forceinline__ void cp_wait() {
    asm volatile("cp.async.wait_group %0;\n" :: "n"(N));
}

// MODE:
//  0 : C[row]        = acc + bias                          (pre-activation, fed to silu_mul)
//  2 : C[row]        = 0.5f*(acc + bias)                   (final output store)
//  3 : C[g*M + row]  = tf32(gelu(acc + bias)), A gathered: token = g + 8*(m0+row)
//  4 : C[g + 8*row] += 0.25f*(acc + bias), A contiguous grouped rows
template<int MODE>
__global__ void __launch_bounds__(256, 2)
gemm_tc(int M, int N, int K,
        const float* __restrict__ A,
        const float* __restrict__ B,
        const float* __restrict__ bias,
        float* __restrict__ C,
        int phase7)
{
    extern __shared__ float sm[];
    float (*As)[BM][ALD]  = (float(*)[BM][ALD])sm;                    // [2][128][36]
    float (*Bs)[BK][BLD]  = (float(*)[BK][BLD])(sm + 2 * BM * ALD);   // [2][32][132]
    float (*St)[16][STLD] = (float(*)[16][STLD])sm;                   // aliases As (epilogue only)

    const int tid  = threadIdx.x;
    const int wid  = tid >> 5;
    const int lane = tid & 31;
    const int wm   = wid >> 1;           // 0..3
    const int wn   = wid & 1;            // 0..1

    const int grp = blockIdx.z;
    const int m0  = blockIdx.y * BM;
    const int n0  = blockIdx.x * BN;

    const float* Bp    = B;
    const float* biasp = bias;
    if (MODE == 3 || MODE == 4) {
        int e = (3 * grp + phase7) & 7;
        Bp    = B    + (size_t)e * K * N;
        biasp = bias + (size_t)e * N;
    }

    // ---- loader mapping ----
    // A: 128x32 tile, 2 threads/row, 16 floats (4x cp.async) each
    const int ar = tid >> 1;
    const int ac = (tid & 1) * 16;
    size_t a_row_g;
    if      (MODE == 3) a_row_g = (size_t)grp + 8u * (size_t)(m0 + ar);
    else if (MODE == 4) a_row_g = (size_t)grp * M + (size_t)(m0 + ar);
    else                a_row_g = (size_t)(m0 + ar);
    const float* Arow = A + a_row_g * (size_t)K + ac;

    // B: 32x128 tile, 8 threads/row, 16 floats (4x cp.async) each
    const int br = tid >> 3;
    const int bc = (tid & 7) * 16;
    const float* Bpos = Bp + (size_t)br * N + n0 + bc;

    uint32_t a_dst[2], b_dst[2];
    #pragma unroll
    for (int s = 0; s < 2; s++) {
        a_dst[s] = (uint32_t)__cvta_generic_to_shared(&As[s][ar][ac]);
        b_dst[s] = (uint32_t)__cvta_generic_to_shared(&Bs[s][br][bc]);
    }

    wmma::fragment<wmma::accumulator, 16, 16, 8, float> acc[2][4];
    #pragma unroll
    for (int i = 0; i < 2; i++)
        #pragma unroll
        for (int j = 0; j < 4; j++) wmma::fill_fragment(acc[i][j], 0.0f);

    const int ktiles = K / BK;

    // prologue: stage tile 0 into buffer 0
    #pragma unroll
    for (int q = 0; q < 4; q++) cp_async16(a_dst[0] + q * 16, Arow + q * 4);
    #pragma unroll
    for (int q = 0; q < 4; q++) cp_async16(b_dst[0] + q * 16, Bpos + q * 4);
    cp_commit();

    for (int t = 0; t < ktiles; t++) {
        const int buf = t & 1;
        if (t + 1 < ktiles) {
            const int nb = buf ^ 1;
            const int k1 = (t + 1) * BK;
            #pragma unroll
            for (int q = 0; q < 4; q++) cp_async16(a_dst[nb] + q * 16, Arow + k1 + q * 4);
            #pragma unroll
            for (int q = 0; q < 4; q++) cp_async16(b_dst[nb] + q * 16, Bpos + (size_t)k1 * N + q * 4);
            cp_commit();
            cp_wait<1>();
        } else {
            cp_wait<0>();
        }
        __syncthreads();

        // inputs are pre-rounded tf32 values: no conversion here, pure LDS->HMMA
        #pragma unroll
        for (int kk = 0; kk < BK / 8; kk++) {
            wmma::fragment<wmma::matrix_a, 16, 16, 8, wmma::precision::tf32, wmma::row_major> af[2];
            wmma::fragment<wmma::matrix_b, 16, 16, 8, wmma::precision::tf32, wmma::row_major> bf[4];
            #pragma unroll
            for (int i = 0; i < 2; i++)
                wmma::load_matrix_sync(af[i], &As[buf][wm * 32 + i * 16][kk * 8], ALD);
            #pragma unroll
            for (int j = 0; j < 4; j++)
                wmma::load_matrix_sync(bf[j], &Bs[buf][kk * 8][wn * 64 + j * 16], BLD);
            #pragma unroll
            for (int i = 0; i < 2; i++)
                #pragma unroll
                for (int j = 0; j < 4; j++)
                    wmma::mma_sync(acc[i][j], af[i], bf[j], acc[i][j]);
        }
        __syncthreads();
    }

    // ---- epilogue: per-fragment staging (St aliases As; mainloop fully synced) ----
    const int sr = lane >> 1;
    const int sc = (lane & 1) * 8;

    #pragma unroll
    for (int i = 0; i < 2; i++) {
        #pragma unroll
        for (int j = 0; j < 4; j++) {
            wmma::store_matrix_sync(&St[wid][0][0], acc[i][j], STLD, wmma::mem_row_major);
            __syncwarp();

            const int rl   = wm * 32 + i * 16 + sr;
            const int ncol = n0 + wn * 64 + j * 16 + sc;

            size_t crow;
            if      (MODE == 3) crow = (size_t)grp * M + (size_t)(m0 + rl);
            else if (MODE == 4) crow = (size_t)grp + 8u * (size_t)(m0 + rl);
            else                crow = (size_t)(m0 + rl);
            float* Cp = C + crow * (size_t)N + ncol;

            float v[8];
            #pragma unroll
            for (int q = 0; q < 8; q++)
                v[q] = St[wid][sr][sc + q] + biasp[ncol + q];

            if (MODE == 4) {
                float4 c0 = *(float4*)Cp;
                float4 c1 = *(float4*)(Cp + 4);
                c0.x += 0.25f * v[0]; c0.y += 0.25f * v[1];
                c0.z += 0.25f * v[2]; c0.w += 0.25f * v[3];
                c1.x += 0.25f * v[4]; c1.y += 0.25f * v[5];
                c1.z += 0.25f * v[6]; c1.w += 0.25f * v[7];
                *(float4*)Cp       = c0;
                *(float4*)(Cp + 4) = c1;
            } else {
                #pragma unroll
                for (int q = 0; q < 8; q++) {
                    if (MODE == 2) v[q] = 0.5f * v[q];
                    if (MODE == 3) {
                        v[q] = 0.5f * v[q] * (1.0f + erff(v[q] * 0.70710678118654752f));
                        v[q] = wmma::__float_to_tf32(v[q]);   // feeds next GEMM
                    }
                }
                *(float4*)Cp       = make_float4(v[0], v[1], v[2], v[3]);
                *(float4*)(Cp + 4) = make_float4(v[4], v[5], v[6], v[7]);
            }
            __syncwarp();
        }
    }
}

// out[i] = tf32_round(in[i]) -- elementwise, float4
__global__ void __launch_bounds__(256)
round_k(const float* __restrict__ in, float* __restrict__ out, size_t n4)
{
    size_t i = (size_t)blockIdx.x * blockDim.x + threadIdx.x;
    if (i < n4) {
        float4 v = ((const float4*)in)[i];
        v.x = wmma::__float_to_tf32(v.x);
        v.y = wmma::__float_to_tf32(v.y);
        v.z = wmma::__float_to_tf32(v.z);
        v.w = wmma::__float_to_tf32(v.w);
        ((float4*)out)[i] = v;
    }
}

// g1 = tf32_round(silu(g1) * g3), elementwise (float4) -- feeds mode-2 GEMM
__global__ void __launch_bounds__(256)
silu_mul_k(float* __restrict__ g1, const float* __restrict__ g3, size_t n4)
{
    size_t i = (size_t)blockIdx.x * blockDim.x + threadIdx.x;
    if (i < n4) {
        float4 a = ((float4*)g1)[i];
        float4 b = ((const float4*)g3)[i];
        a.x = wmma::__float_to_tf32((a.x / (1.f + expf(-a.x))) * b.x);
        a.y = wmma::__float_to_tf32((a.y / (1.f + expf(-a.y))) * b.y);
        a.z = wmma::__float_to_tf32((a.z / (1.f + expf(-a.z))) * b.z);
        a.w = wmma::__float_to_tf32((a.w / (1.f + expf(-a.w))) * b.w);
        ((float4*)g1)[i] = a;
    }
}

extern "C" void kernel_launch(void* const* d_in, const int* in_sizes, int n_in,
                              void* d_out, int out_size)
{
    const float* x   = (const float*)d_in[0];
    // d_in[1] = t_emb (unused by the reference)
    const float* sw1 = (const float*)d_in[2];
    const float* sb1 = (const float*)d_in[3];
    const float* sw3 = (const float*)d_in[4];
    const float* sb3 = (const float*)d_in[5];
    const float* sw2 = (const float*)d_in[6];
    const float* sb2 = (const float*)d_in[7];
    const float* w1  = (const float*)d_in[8];
    const float* b1  = (const float*)d_in[9];
    const float* w2  = (const float*)d_in[10];
    const float* b2  = (const float*)d_in[11];
    float* out = (float*)d_out;

    float *g1p, *g3p, *hp, *wT, *xr;
    cudaGetSymbolAddress((void**)&g1p, g_g1);
    cudaGetSymbolAddress((void**)&g3p, g_g3);
    cudaGetSymbolAddress((void**)&hp,  g_h);
    cudaGetSymbolAddress((void**)&wT,  g_wT);
    cudaGetSymbolAddress((void**)&xr,  g_xr);

    cudaFuncSetAttribute(gemm_tc<0>, cudaFuncAttributeMaxDynamicSharedMemorySize, SMEM_BYTES);
    cudaFuncSetAttribute(gemm_tc<2>, cudaFuncAttributeMaxDynamicSharedMemorySize, SMEM_BYTES);
    cudaFuncSetAttribute(gemm_tc<3>, cudaFuncAttributeMaxDynamicSharedMemorySize, SMEM_BYTES);
    cudaFuncSetAttribute(gemm_tc<4>, cudaFuncAttributeMaxDynamicSharedMemorySize, SMEM_BYTES);

    const dim3 blk(256);
    auto rnd = [&](const float* src, float* dst, size_t n) {
        size_t n4 = n / 4;
        round_k<<<(unsigned)((n4 + 255) / 256), blk>>>(src, dst, n4);
    };

    // pre-round all GEMM operands to tf32 (rna), stored as fp32
    rnd(x,   xr,           (size_t)NTOK * CDIM);
    rnd(sw1, wT + OFF_SW1, (size_t)CDIM * HS);
    rnd(sw3, wT + OFF_SW3, (size_t)CDIM * HS);
    rnd(sw2, wT + OFF_SW2, (size_t)HS * CDIM);
    rnd(w1,  wT + OFF_W1,  (size_t)8 * CDIM * HR);
    rnd(w2,  wT + OFF_W2,  (size_t)8 * HR * CDIM);

    // Shared SwiGLU: g1 = x@sw1+sb1 ; g3 = x@sw3+sb3
    gemm_tc<0><<<dim3(HS / BN, NTOK / BM, 1), blk, SMEM_BYTES>>>(NTOK, HS, CDIM, xr, wT + OFF_SW1, sb1, g1p, 0);
    gemm_tc<0><<<dim3(HS / BN, NTOK / BM, 1), blk, SMEM_BYTES>>>(NTOK, HS, CDIM, xr, wT + OFF_SW3, sb3, g3p, 0);

    // g1 = tf32(silu(g1)*g3)
    const size_t n4 = (size_t)NTOK * HS / 4;
    silu_mul_k<<<(unsigned)((n4 + 255) / 256), blk>>>(g1p, g3p, n4);

    // out = 0.5*(g1@sw2 + sb2)   (writes every output element)
    gemm_tc<2><<<dim3(CDIM / BN, NTOK / BM, 1), blk, SMEM_BYTES>>>(NTOK, CDIM, HS, g1p, wT + OFF_SW2, sb2, out, 0);

    // Routed experts, k = 0 (phase 0) and k = 1 (phase 7)
    for (int phase = 0; phase <= 7; phase += 7) {
        gemm_tc<3><<<dim3(HR / BN, MPG / BM, 8), blk, SMEM_BYTES>>>(MPG, HR, CDIM, xr, wT + OFF_W1, b1, hp, phase);
        gemm_tc<4><<<dim3(CDIM / BN, MPG / BM, 8), blk, SMEM_BYTES>>>(MPG, CDIM, HR, hp, wT + OFF_W2, b2, out, phase);
    }
}